// round 15
// baseline (speedup 1.0000x reference)
#include <cuda_runtime.h>

// PixCorr: per-row Pearson correlation over [256, 196608] fp32 rows, then
// mean over rows.
//
// R10 two-kernel PDL structure (best measured: 61.5us), with the dependency
// release replaced by a ticket-spin handoff:
//  - Row kernel (one CTA per row, 256 x 1024, plain cached float4 loads):
//    after computing corr, lane0 stores g_corr[row], __threadfence (release),
//    atomicAdd(&g_ticket, 1).
//  - Mean kernel (1 x 32, PDL-launched with the entry trigger so it is
//    resident during the row kernel's wave 2): spins on g_ticket == 256
//    (release/acquire via fence+atomic, NOT grid completion), reduces the
//    256 corrs in fixed order, writes d_out[0], resets the ticket for the
//    next graph replay. This skips the multi-us grid-teardown release path.
//  - Co-residency is always possible (32 thr / ~1KB regs beside the 1024-thr
//    row CTA), so the spin cannot deadlock.

#define NROWS   256
#define D_ELEMS 196608          // 3*256*256
#define NVEC    (D_ELEMS / 4)   // 49152 float4 per row
#define THREADS 1024
#define EPS     1e-6f

__device__ float                 g_corr[NROWS];
__device__ volatile unsigned int g_ticket;   // zero-initialized at module load

__device__ __forceinline__ float warp_sum(float v) {
    v += __shfl_xor_sync(0xFFFFFFFFu, v, 16);
    v += __shfl_xor_sync(0xFFFFFFFFu, v, 8);
    v += __shfl_xor_sync(0xFFFFFFFFu, v, 4);
    v += __shfl_xor_sync(0xFFFFFFFFu, v, 2);
    v += __shfl_xor_sync(0xFFFFFFFFu, v, 1);
    return v;
}

__global__ __launch_bounds__(THREADS, 1)
void pixcorr_row_kernel(const float* __restrict__ preds,
                        const float* __restrict__ targets) {
    // Allow the dependent mean kernel to launch and park immediately.
    cudaTriggerProgrammaticLaunchCompletion();

    const int row = blockIdx.x;
    const float4* __restrict__ z4 =
        reinterpret_cast<const float4*>(targets + (size_t)row * D_ELEMS);
    const float4* __restrict__ b4 =
        reinterpret_cast<const float4*>(preds + (size_t)row * D_ELEMS);

    float sz = 0.f, sb = 0.f, szz = 0.f, sbb = 0.f, szb = 0.f;

    // 48 iterations per thread, fully coalesced plain cached float4 loads.
    #pragma unroll 4
    for (int i = threadIdx.x; i < NVEC; i += THREADS) {
        float4 zv = z4[i];
        float4 bv = b4[i];
        sz  += (zv.x + zv.y) + (zv.z + zv.w);
        sb  += (bv.x + bv.y) + (bv.z + bv.w);
        szz  = fmaf(zv.x, zv.x, fmaf(zv.y, zv.y, fmaf(zv.z, zv.z, fmaf(zv.w, zv.w, szz))));
        sbb  = fmaf(bv.x, bv.x, fmaf(bv.y, bv.y, fmaf(bv.z, bv.z, fmaf(bv.w, bv.w, sbb))));
        szb  = fmaf(zv.x, bv.x, fmaf(zv.y, bv.y, fmaf(zv.z, bv.z, fmaf(zv.w, bv.w, szb))));
    }

    sz  = warp_sum(sz);
    sb  = warp_sum(sb);
    szz = warp_sum(szz);
    sbb = warp_sum(sbb);
    szb = warp_sum(szb);

    __shared__ float sh[5][THREADS / 32];
    const int lane = threadIdx.x & 31;
    const int wid  = threadIdx.x >> 5;
    if (lane == 0) {
        sh[0][wid] = sz;  sh[1][wid] = sb;
        sh[2][wid] = szz; sh[3][wid] = sbb; sh[4][wid] = szb;
    }
    __syncthreads();

    if (threadIdx.x < 32) {
        float a0 = warp_sum(sh[0][lane]);
        float a1 = warp_sum(sh[1][lane]);
        float a2 = warp_sum(sh[2][lane]);
        float a3 = warp_sum(sh[3][lane]);
        float a4 = warp_sum(sh[4][lane]);
        if (lane == 0) {
            const float invD = 1.0f / (float)D_ELEMS;
            float cov = a4 - a0 * a1 * invD;
            float vz  = fmaxf(a2 - a0 * a0 * invD, 0.f);
            float vb  = fmaxf(a3 - a1 * a1 * invD, 0.f);
            g_corr[row] = cov / (sqrtf(vz) * sqrtf(vb) + EPS);
            __threadfence();                         // release g_corr[row]
            atomicAdd((unsigned int*)&g_ticket, 1u); // publish
        }
    }
}

__global__ void pixcorr_mean_kernel(float* __restrict__ out) {
    const int lane = threadIdx.x;  // 0..31

    // Fast handoff: wait for all 256 row-CTA publishes (fence+atomic release
    // on the producer side; fence below is the acquire). This completes
    // ahead of the primary grid's teardown/flush path.
    if (lane == 0) {
        while (g_ticket < (unsigned int)NROWS) { /* spin */ }
    }
    __syncwarp();
    __threadfence();  // acquire: all g_corr stores are now visible

    // Each lane sums 8 of the 256 corrs (fixed order), then shfl-reduce.
    float s = 0.f;
    #pragma unroll
    for (int i = 0; i < NROWS / 32; i++)
        s += g_corr[lane + i * 32];
    s = warp_sum(s);
    if (lane == 0) {
        out[0] = s * (1.0f / (float)NROWS);
        g_ticket = 0;   // reset for next graph replay (stream-ordered)
        __threadfence();
    }
}

extern "C" void kernel_launch(void* const* d_in, const int* in_sizes, int n_in,
                              void* d_out, int out_size) {
    const float* preds   = (const float*)d_in[0];
    const float* targets = (const float*)d_in[1];
    float* out = (float*)d_out;

    pixcorr_row_kernel<<<NROWS, THREADS>>>(preds, targets);

    // PDL launch: the mean kernel becomes resident during the row kernel's
    // execution and parks in the ticket spin.
    cudaLaunchConfig_t cfg = {};
    cfg.gridDim  = dim3(1, 1, 1);
    cfg.blockDim = dim3(32, 1, 1);
    cfg.dynamicSmemBytes = 0;
    cfg.stream = 0;  // same stream as the row kernel
    cudaLaunchAttribute attr[1];
    attr[0].id = cudaLaunchAttributeProgrammaticStreamSerialization;
    attr[0].val.programmaticStreamSerializationAllowed = 1;
    cfg.attrs = attr;
    cfg.numAttrs = 1;

    cudaError_t e = cudaLaunchKernelEx(&cfg, pixcorr_mean_kernel, out);
    if (e != cudaSuccess) {
        // Fallback: plain serialized launch (ticket is already 256 at entry).
        pixcorr_mean_kernel<<<1, 32>>>(out);
    }
}

// round 16
// speedup vs baseline: 1.0329x; 1.0329x over previous
#include <cuda_runtime.h>

// PixCorr: per-row Pearson correlation over [256, 196608] fp32 rows, then
// mean over rows.
//
// CHAMPION CONFIG (R10, 61.5us): two kernels, PDL-overlapped tail.
//  - Row kernel: one CTA per row (256 x 1024), plain cached float4 loads,
//    unroll 4, 5 running sums, block reduce, corr -> g_corr[row].
//    Measured at the chip's effective dual-stream HBM read ceiling
//    (~6.5 TB/s => ~61us for 403 MB); no load-path or grid-shape variant
//    measured faster across 13 rounds.
//  - Mean kernel: 256 threads, launched with programmatic stream
//    serialization (PDL); opens with cudaGridDependencySynchronize(), so
//    its launch setup overlaps the row kernel and only the ~1us reduction
//    remains serialized.

#define NROWS   256
#define D_ELEMS 196608          // 3*256*256
#define NVEC    (D_ELEMS / 4)   // 49152 float4 per row
#define THREADS 1024
#define EPS     1e-6f

__device__ float g_corr[NROWS];

__device__ __forceinline__ float warp_sum(float v) {
    v += __shfl_xor_sync(0xFFFFFFFFu, v, 16);
    v += __shfl_xor_sync(0xFFFFFFFFu, v, 8);
    v += __shfl_xor_sync(0xFFFFFFFFu, v, 4);
    v += __shfl_xor_sync(0xFFFFFFFFu, v, 2);
    v += __shfl_xor_sync(0xFFFFFFFFu, v, 1);
    return v;
}

__global__ __launch_bounds__(THREADS, 1)
void pixcorr_row_kernel(const float* __restrict__ preds,
                        const float* __restrict__ targets) {
    const int row = blockIdx.x;
    const float4* __restrict__ z4 =
        reinterpret_cast<const float4*>(targets + (size_t)row * D_ELEMS);
    const float4* __restrict__ b4 =
        reinterpret_cast<const float4*>(preds + (size_t)row * D_ELEMS);

    float sz = 0.f, sb = 0.f, szz = 0.f, sbb = 0.f, szb = 0.f;

    // 48 iterations per thread, fully coalesced plain cached float4 loads.
    #pragma unroll 4
    for (int i = threadIdx.x; i < NVEC; i += THREADS) {
        float4 zv = z4[i];
        float4 bv = b4[i];
        sz  += (zv.x + zv.y) + (zv.z + zv.w);
        sb  += (bv.x + bv.y) + (bv.z + bv.w);
        szz  = fmaf(zv.x, zv.x, fmaf(zv.y, zv.y, fmaf(zv.z, zv.z, fmaf(zv.w, zv.w, szz))));
        sbb  = fmaf(bv.x, bv.x, fmaf(bv.y, bv.y, fmaf(bv.z, bv.z, fmaf(bv.w, bv.w, sbb))));
        szb  = fmaf(zv.x, bv.x, fmaf(zv.y, bv.y, fmaf(zv.z, bv.z, fmaf(zv.w, bv.w, szb))));
    }

    sz  = warp_sum(sz);
    sb  = warp_sum(sb);
    szz = warp_sum(szz);
    sbb = warp_sum(sbb);
    szb = warp_sum(szb);

    __shared__ float sh[5][THREADS / 32];
    const int lane = threadIdx.x & 31;
    const int wid  = threadIdx.x >> 5;
    if (lane == 0) {
        sh[0][wid] = sz;  sh[1][wid] = sb;
        sh[2][wid] = szz; sh[3][wid] = sbb; sh[4][wid] = szb;
    }
    __syncthreads();

    if (threadIdx.x < 32) {
        float a0 = warp_sum(sh[0][lane]);
        float a1 = warp_sum(sh[1][lane]);
        float a2 = warp_sum(sh[2][lane]);
        float a3 = warp_sum(sh[3][lane]);
        float a4 = warp_sum(sh[4][lane]);
        if (lane == 0) {
            const float invD = 1.0f / (float)D_ELEMS;
            float cov = a4 - a0 * a1 * invD;
            float vz  = fmaxf(a2 - a0 * a0 * invD, 0.f);
            float vb  = fmaxf(a3 - a1 * a1 * invD, 0.f);
            g_corr[row] = cov / (sqrtf(vz) * sqrtf(vb) + EPS);
        }
    }
}

__global__ void pixcorr_mean_kernel(float* __restrict__ out) {
    // PDL: wait for the primary grid's completion + memory flush before
    // reading g_corr.
    cudaGridDependencySynchronize();

    // 256 threads = 8 warps
    float v = g_corr[threadIdx.x];
    v = warp_sum(v);
    __shared__ float sh[8];
    const int lane = threadIdx.x & 31;
    const int wid  = threadIdx.x >> 5;
    if (lane == 0) sh[wid] = v;
    __syncthreads();
    if (threadIdx.x == 0) {
        float s = 0.f;
        #pragma unroll
        for (int i = 0; i < 8; i++) s += sh[i];
        out[0] = s * (1.0f / (float)NROWS);
    }
}

extern "C" void kernel_launch(void* const* d_in, const int* in_sizes, int n_in,
                              void* d_out, int out_size) {
    const float* preds   = (const float*)d_in[0];
    const float* targets = (const float*)d_in[1];
    float* out = (float*)d_out;

    pixcorr_row_kernel<<<NROWS, THREADS>>>(preds, targets);

    // Launch the mean kernel with programmatic stream serialization so its
    // launch overhead overlaps the row kernel's execution.
    cudaLaunchConfig_t cfg = {};
    cfg.gridDim  = dim3(1, 1, 1);
    cfg.blockDim = dim3(NROWS, 1, 1);
    cfg.dynamicSmemBytes = 0;
    cfg.stream = 0;  // legacy default stream (same as <<<>>> above)
    cudaLaunchAttribute attr[1];
    attr[0].id = cudaLaunchAttributeProgrammaticStreamSerialization;
    attr[0].val.programmaticStreamSerializationAllowed = 1;
    cfg.attrs = attr;
    cfg.numAttrs = 1;

    cudaError_t e = cudaLaunchKernelEx(&cfg, pixcorr_mean_kernel, out);
    if (e != cudaSuccess) {
        // Fallback: plain serialized launch (identical semantics).
        pixcorr_mean_kernel<<<1, NROWS>>>(out);
    }
}